// round 4
// baseline (speedup 1.0000x reference)
#include <cuda_runtime.h>

#define NN 100000
#define EE 1600000
#define D 64
#define BN_EPS 1e-5f
#define SCAN_T 1024
#define CHUNK ((NN + SCAN_T - 1) / SCAN_T)   // 98

// Scratch (device globals — no allocation allowed).
__device__ __align__(16) float g_h [NN * D];
__device__ __align__(16) float g_h1[NN * D];
__device__ __align__(16) float g_sum[D];
__device__ __align__(16) float g_sumsq[D];
__device__ __align__(16) int   g_deg[NN];
__device__ __align__(16) int   g_rowptr[NN + 1];
__device__ __align__(16) int   g_cursor[NN];
__device__ __align__(16) int   g_col[EE];

// ---------------------------------------------------------------------------
// 1: zero degree counters + BN accumulators
// ---------------------------------------------------------------------------
__global__ void k_zero() {
    int i = blockIdx.x * blockDim.x + threadIdx.x;
    if (i < NN) g_deg[i] = 0;
    if (i < D) { g_sum[i] = 0.f; g_sumsq[i] = 0.f; }
}

// ---------------------------------------------------------------------------
// 2: degree histogram over destinations (edge_index is int32: JAX demotes
//    int64 -> int32 without jax_enable_x64)
// ---------------------------------------------------------------------------
__global__ void k_deg(const int* __restrict__ ei) {
    int e = blockIdx.x * blockDim.x + threadIdx.x;
    if (e >= EE) return;
    int dst = ei[EE + e];
    atomicAdd(&g_deg[dst], 1);
}

// ---------------------------------------------------------------------------
// 3: single-block chunked exclusive scan -> rowptr, cursor
// ---------------------------------------------------------------------------
__global__ void __launch_bounds__(SCAN_T) k_scan() {
    __shared__ int sh[SCAN_T];
    const int t = threadIdx.x;
    const int start = t * CHUNK;
    const int end = min(start + CHUNK, NN);
    int s = 0;
    for (int i = start; i < end; i++) s += g_deg[i];
    sh[t] = s;
    __syncthreads();
    // Hillis-Steele inclusive scan over per-thread sums
    for (int off = 1; off < SCAN_T; off <<= 1) {
        int add = (t >= off) ? sh[t - off] : 0;
        __syncthreads();
        sh[t] += add;
        __syncthreads();
    }
    int run = (t == 0) ? 0 : sh[t - 1];
    for (int i = start; i < end; i++) {
        g_rowptr[i] = run;
        g_cursor[i] = run;
        run += g_deg[i];
    }
    if (start < NN && end == NN) g_rowptr[NN] = run;
}

// ---------------------------------------------------------------------------
// 4: scatter src indices into CSR col array
// ---------------------------------------------------------------------------
__global__ void k_fill(const int* __restrict__ ei) {
    int e = blockIdx.x * blockDim.x + threadIdx.x;
    if (e >= EE) return;
    int src = ei[e];
    int dst = ei[EE + e];
    int pos = atomicAdd(&g_cursor[dst], 1);
    g_col[pos] = src;
}

// ---------------------------------------------------------------------------
// 5: gather. One warp per node; lane owns columns {lane, lane+32}.
//    h[n] = (1+eps)*x[n] + sum_{s in nbrs(n)} x[s]
// ---------------------------------------------------------------------------
__global__ void __launch_bounds__(256) k_gather(const float* __restrict__ x,
                                                const float* __restrict__ eps_p) {
    const int w = (blockIdx.x * blockDim.x + threadIdx.x) >> 5;
    const int lane = threadIdx.x & 31;
    if (w >= NN) return;
    const int beg = g_rowptr[w];
    const int end = g_rowptr[w + 1];
    float a0 = 0.f, a1 = 0.f, b0 = 0.f, b1 = 0.f;
    int j = beg;
    // 2-way unroll: two independent accumulator pairs keep more loads in flight
    for (; j + 1 < end; j += 2) {
        int s0 = g_col[j];
        int s1 = g_col[j + 1];
        a0 += x[(size_t)s0 * D + lane];
        a1 += x[(size_t)s0 * D + 32 + lane];
        b0 += x[(size_t)s1 * D + lane];
        b1 += x[(size_t)s1 * D + 32 + lane];
    }
    if (j < end) {
        int s0 = g_col[j];
        a0 += x[(size_t)s0 * D + lane];
        a1 += x[(size_t)s0 * D + 32 + lane];
    }
    const float sc = 1.f + *eps_p;
    g_h[(size_t)w * D + lane]      = sc * x[(size_t)w * D + lane]      + a0 + b0;
    g_h[(size_t)w * D + 32 + lane] = sc * x[(size_t)w * D + 32 + lane] + a1 + b1;
}

// ---------------------------------------------------------------------------
// 6: h1 = h @ W1 + b1. One row per thread, W1 in shared (broadcast LDS).
// ---------------------------------------------------------------------------
__global__ void __launch_bounds__(128) k_gemm1(const float* __restrict__ W1,
                                               const float* __restrict__ b1) {
    __shared__ __align__(16) float Ws[D * D];
    __shared__ __align__(16) float bs[D];
    const int tid = threadIdx.x;
    for (int i = tid; i < D * D; i += blockDim.x) Ws[i] = W1[i];
    if (tid < D) bs[tid] = b1[tid];
    __syncthreads();

    const int row = blockIdx.x * blockDim.x + tid;
    if (row >= NN) return;

    float acc[D];
#pragma unroll
    for (int j = 0; j < D; j++) acc[j] = 0.f;

    const float4* __restrict__ hr = (const float4*)(g_h + (size_t)row * D);
    for (int k4 = 0; k4 < D / 4; k4++) {
        float4 hv = hr[k4];
#pragma unroll
        for (int kk = 0; kk < 4; kk++) {
            const float hk = ((const float*)&hv)[kk];
            const float4* wrow = (const float4*)&Ws[(k4 * 4 + kk) * D];
#pragma unroll
            for (int j4 = 0; j4 < D / 4; j4++) {
                float4 w = wrow[j4];
                acc[j4 * 4 + 0] += hk * w.x;
                acc[j4 * 4 + 1] += hk * w.y;
                acc[j4 * 4 + 2] += hk * w.z;
                acc[j4 * 4 + 3] += hk * w.w;
            }
        }
    }
    float4* out = (float4*)(g_h1 + (size_t)row * D);
#pragma unroll
    for (int j4 = 0; j4 < D / 4; j4++) {
        float4 o;
        o.x = acc[j4 * 4 + 0] + bs[j4 * 4 + 0];
        o.y = acc[j4 * 4 + 1] + bs[j4 * 4 + 1];
        o.z = acc[j4 * 4 + 2] + bs[j4 * 4 + 2];
        o.w = acc[j4 * 4 + 3] + bs[j4 * 4 + 3];
        out[j4] = o;
    }
}

// ---------------------------------------------------------------------------
// 7: per-column sum / sumsq of h1
// ---------------------------------------------------------------------------
__global__ void k_stats() {
    const int col = threadIdx.x & (D - 1);
    const int rib = threadIdx.x >> 6;                     // row-in-block 0..3
    const int stride = (blockDim.x / D) * gridDim.x;
    float s = 0.f, sq = 0.f;
    for (int r = blockIdx.x * (blockDim.x / D) + rib; r < NN; r += stride) {
        float v = g_h1[(size_t)r * D + col];
        s += v; sq += v * v;
    }
    __shared__ __align__(16) float sh[256];
    __shared__ __align__(16) float shq[256];
    sh[threadIdx.x] = s; shq[threadIdx.x] = sq;
    __syncthreads();
    if (threadIdx.x < D) {
        float ts = sh[threadIdx.x] + sh[threadIdx.x + 64] +
                   sh[threadIdx.x + 128] + sh[threadIdx.x + 192];
        float tq = shq[threadIdx.x] + shq[threadIdx.x + 64] +
                   shq[threadIdx.x + 128] + shq[threadIdx.x + 192];
        atomicAdd(&g_sum[threadIdx.x], ts);
        atomicAdd(&g_sumsq[threadIdx.x], tq);
    }
}

// ---------------------------------------------------------------------------
// 8: out = relu(BN(h1)) @ W2 + b2, BN folded into per-column scale/shift
// ---------------------------------------------------------------------------
__global__ void __launch_bounds__(128) k_gemm2(const float* __restrict__ W2,
                                               const float* __restrict__ b2,
                                               const float* __restrict__ gamma,
                                               const float* __restrict__ beta,
                                               float* __restrict__ out) {
    __shared__ __align__(16) float Ws[D * D];
    __shared__ __align__(16) float scl[D];
    __shared__ __align__(16) float sft[D];
    __shared__ __align__(16) float bs[D];
    const int tid = threadIdx.x;
    for (int i = tid; i < D * D; i += blockDim.x) Ws[i] = W2[i];
    if (tid < D) {
        const float inv_n = 1.f / (float)NN;
        float mean = g_sum[tid] * inv_n;
        float var  = g_sumsq[tid] * inv_n - mean * mean;
        float rstd = rsqrtf(var + BN_EPS);
        float s = rstd * gamma[tid];
        scl[tid] = s;
        sft[tid] = beta[tid] - mean * s;
        bs[tid]  = b2[tid];
    }
    __syncthreads();

    const int row = blockIdx.x * blockDim.x + tid;
    if (row >= NN) return;

    float acc[D];
#pragma unroll
    for (int j = 0; j < D; j++) acc[j] = 0.f;

    const float4* __restrict__ hr = (const float4*)(g_h1 + (size_t)row * D);
    for (int k4 = 0; k4 < D / 4; k4++) {
        float4 hv = hr[k4];
#pragma unroll
        for (int kk = 0; kk < 4; kk++) {
            const int k = k4 * 4 + kk;
            float hk = ((const float*)&hv)[kk];
            hk = fmaxf(hk * scl[k] + sft[k], 0.f);        // BN + ReLU
            const float4* wrow = (const float4*)&Ws[k * D];
#pragma unroll
            for (int j4 = 0; j4 < D / 4; j4++) {
                float4 w = wrow[j4];
                acc[j4 * 4 + 0] += hk * w.x;
                acc[j4 * 4 + 1] += hk * w.y;
                acc[j4 * 4 + 2] += hk * w.z;
                acc[j4 * 4 + 3] += hk * w.w;
            }
        }
    }
    float4* o4 = (float4*)(out + (size_t)row * D);
#pragma unroll
    for (int j4 = 0; j4 < D / 4; j4++) {
        float4 o;
        o.x = acc[j4 * 4 + 0] + bs[j4 * 4 + 0];
        o.y = acc[j4 * 4 + 1] + bs[j4 * 4 + 1];
        o.z = acc[j4 * 4 + 2] + bs[j4 * 4 + 2];
        o.w = acc[j4 * 4 + 3] + bs[j4 * 4 + 3];
        o4[j4] = o;
    }
}

// ---------------------------------------------------------------------------
extern "C" void kernel_launch(void* const* d_in, const int* in_sizes, int n_in,
                              void* d_out, int out_size) {
    const float* x     = (const float*)d_in[0];
    const int*   ei    = (const int*)  d_in[1];   // int32! (JAX demotes int64)
    const float* eps   = (const float*)d_in[2];
    const float* W1    = (const float*)d_in[3];
    const float* b1    = (const float*)d_in[4];
    const float* gamma = (const float*)d_in[5];
    const float* beta  = (const float*)d_in[6];
    const float* W2    = (const float*)d_in[7];
    const float* b2    = (const float*)d_in[8];
    float* out = (float*)d_out;

    k_zero  <<<(NN + 255) / 256, 256>>>();
    k_deg   <<<(EE + 255) / 256, 256>>>(ei);
    k_scan  <<<1, SCAN_T>>>();
    k_fill  <<<(EE + 255) / 256, 256>>>(ei);
    k_gather<<<(NN * 32 + 255) / 256, 256>>>(x, eps);
    k_gemm1 <<<(NN + 127) / 128, 128>>>(W1, b1);
    k_stats <<<256, 256>>>();
    k_gemm2 <<<(NN + 127) / 128, 128>>>(W2, b2, gamma, beta, out);
}

// round 5
// speedup vs baseline: 1.7934x; 1.7934x over previous
#include <cuda_runtime.h>

#define NN 100000
#define EE 1600000
#define D 64
#define BN_EPS 1e-5f
#define SB 1024
#define NBLK ((NN + SB - 1) / SB)   // 98

// Scratch (device globals — no allocation allowed).
__device__ __align__(16) float g_h [NN * D];
__device__ __align__(16) float g_h1[NN * D];
__device__ __align__(16) float g_sum[D];
__device__ __align__(16) float g_sumsq[D];
__device__ __align__(16) int   g_deg[NN];
__device__ __align__(16) int   g_rowptr[NN + 1];
__device__ __align__(16) int   g_cursor[NN];
__device__ __align__(16) int   g_col[EE];
__device__ __align__(16) int   g_bsum[NBLK];
__device__ __align__(16) int   g_boff[NBLK];

// ---------------------------------------------------------------------------
// 1: zero degree counters + BN accumulators
// ---------------------------------------------------------------------------
__global__ void k_zero() {
    int i = blockIdx.x * blockDim.x + threadIdx.x;
    if (i < NN) g_deg[i] = 0;
    if (i < D) { g_sum[i] = 0.f; g_sumsq[i] = 0.f; }
}

// ---------------------------------------------------------------------------
// 2: degree histogram over destinations (edge_index is int32)
// ---------------------------------------------------------------------------
__global__ void k_deg(const int* __restrict__ ei) {
    int e = blockIdx.x * blockDim.x + threadIdx.x;
    if (e >= EE) return;
    atomicAdd(&g_deg[ei[EE + e]], 1);
}

// ---------------------------------------------------------------------------
// 3a: per-block degree sums (coalesced, full chip)
// ---------------------------------------------------------------------------
__global__ void __launch_bounds__(SB) k_scan_a() {
    __shared__ int sh[SB];
    int i = blockIdx.x * SB + threadIdx.x;
    sh[threadIdx.x] = (i < NN) ? g_deg[i] : 0;
    __syncthreads();
    for (int off = SB / 2; off > 0; off >>= 1) {
        if (threadIdx.x < off) sh[threadIdx.x] += sh[threadIdx.x + off];
        __syncthreads();
    }
    if (threadIdx.x == 0) g_bsum[blockIdx.x] = sh[0];
}

// ---------------------------------------------------------------------------
// 3b: exclusive scan of the 98 block sums (one tiny block)
// ---------------------------------------------------------------------------
__global__ void __launch_bounds__(128) k_scan_b() {
    __shared__ int sh[128];
    int t = threadIdx.x;
    sh[t] = (t < NBLK) ? g_bsum[t] : 0;
    __syncthreads();
    for (int off = 1; off < 128; off <<= 1) {
        int add = (t >= off) ? sh[t - off] : 0;
        __syncthreads();
        sh[t] += add;
        __syncthreads();
    }
    if (t < NBLK) g_boff[t] = (t == 0) ? 0 : sh[t - 1];
    if (t == 0) g_rowptr[NN] = EE;   // total degree is exactly E
}

// ---------------------------------------------------------------------------
// 3c: block-local exclusive scan + block offset -> rowptr, cursor
// ---------------------------------------------------------------------------
__global__ void __launch_bounds__(SB) k_scan_c() {
    __shared__ int sh[SB];
    const int t = threadIdx.x;
    const int i = blockIdx.x * SB + t;
    const int v = (i < NN) ? g_deg[i] : 0;
    sh[t] = v;
    __syncthreads();
    // Hillis-Steele inclusive scan
    for (int off = 1; off < SB; off <<= 1) {
        int add = (t >= off) ? sh[t - off] : 0;
        __syncthreads();
        sh[t] += add;
        __syncthreads();
    }
    if (i < NN) {
        int excl = g_boff[blockIdx.x] + sh[t] - v;
        g_rowptr[i] = excl;
        g_cursor[i] = excl;
    }
}

// ---------------------------------------------------------------------------
// 4: scatter src indices into CSR col array
// ---------------------------------------------------------------------------
__global__ void k_fill(const int* __restrict__ ei) {
    int e = blockIdx.x * blockDim.x + threadIdx.x;
    if (e >= EE) return;
    int src = ei[e];
    int dst = ei[EE + e];
    int pos = atomicAdd(&g_cursor[dst], 1);
    g_col[pos] = src;
}

// ---------------------------------------------------------------------------
// 5: gather. One warp per node; lane owns a float2 (columns 2*lane, 2*lane+1).
//    4-way edge unroll -> 8 independent loads in flight per lane.
// ---------------------------------------------------------------------------
__global__ void __launch_bounds__(256) k_gather(const float* __restrict__ x,
                                                const float* __restrict__ eps_p) {
    const int w = (blockIdx.x * blockDim.x + threadIdx.x) >> 5;
    const int lane = threadIdx.x & 31;
    if (w >= NN) return;
    const int beg = g_rowptr[w];
    const int end = g_rowptr[w + 1];
    const float2* __restrict__ x2 = (const float2*)x;   // row = 32 float2

    float ax = 0.f, ay = 0.f, bx = 0.f, by = 0.f;
    float cx = 0.f, cy = 0.f, dx = 0.f, dy = 0.f;
    int j = beg;
    for (; j + 3 < end; j += 4) {
        int s0 = g_col[j],     s1 = g_col[j + 1];
        int s2 = g_col[j + 2], s3 = g_col[j + 3];
        float2 v0 = x2[(size_t)s0 * 32 + lane];
        float2 v1 = x2[(size_t)s1 * 32 + lane];
        float2 v2 = x2[(size_t)s2 * 32 + lane];
        float2 v3 = x2[(size_t)s3 * 32 + lane];
        ax += v0.x; ay += v0.y;
        bx += v1.x; by += v1.y;
        cx += v2.x; cy += v2.y;
        dx += v3.x; dy += v3.y;
    }
    for (; j < end; j++) {
        int s0 = g_col[j];
        float2 v0 = x2[(size_t)s0 * 32 + lane];
        ax += v0.x; ay += v0.y;
    }
    const float sc = 1.f + *eps_p;
    float2 xv = x2[(size_t)w * 32 + lane];
    float2 o;
    o.x = sc * xv.x + ((ax + bx) + (cx + dx));
    o.y = sc * xv.y + ((ay + by) + (cy + dy));
    ((float2*)g_h)[(size_t)w * 32 + lane] = o;
}

// ---------------------------------------------------------------------------
// 6: h1 = h @ W1 + b1. One row per thread, W1 in shared (broadcast LDS).
// ---------------------------------------------------------------------------
__global__ void __launch_bounds__(128) k_gemm1(const float* __restrict__ W1,
                                               const float* __restrict__ b1) {
    __shared__ __align__(16) float Ws[D * D];
    __shared__ __align__(16) float bs[D];
    const int tid = threadIdx.x;
    for (int i = tid; i < D * D; i += blockDim.x) Ws[i] = W1[i];
    if (tid < D) bs[tid] = b1[tid];
    __syncthreads();

    const int row = blockIdx.x * blockDim.x + tid;
    if (row >= NN) return;

    float acc[D];
#pragma unroll
    for (int j = 0; j < D; j++) acc[j] = 0.f;

    const float4* __restrict__ hr = (const float4*)(g_h + (size_t)row * D);
    for (int k4 = 0; k4 < D / 4; k4++) {
        float4 hv = hr[k4];
#pragma unroll
        for (int kk = 0; kk < 4; kk++) {
            const float hk = ((const float*)&hv)[kk];
            const float4* wrow = (const float4*)&Ws[(k4 * 4 + kk) * D];
#pragma unroll
            for (int j4 = 0; j4 < D / 4; j4++) {
                float4 w = wrow[j4];
                acc[j4 * 4 + 0] += hk * w.x;
                acc[j4 * 4 + 1] += hk * w.y;
                acc[j4 * 4 + 2] += hk * w.z;
                acc[j4 * 4 + 3] += hk * w.w;
            }
        }
    }
    float4* out = (float4*)(g_h1 + (size_t)row * D);
#pragma unroll
    for (int j4 = 0; j4 < D / 4; j4++) {
        float4 o;
        o.x = acc[j4 * 4 + 0] + bs[j4 * 4 + 0];
        o.y = acc[j4 * 4 + 1] + bs[j4 * 4 + 1];
        o.z = acc[j4 * 4 + 2] + bs[j4 * 4 + 2];
        o.w = acc[j4 * 4 + 3] + bs[j4 * 4 + 3];
        out[j4] = o;
    }
}

// ---------------------------------------------------------------------------
// 7: per-column sum / sumsq of h1
// ---------------------------------------------------------------------------
__global__ void k_stats() {
    const int col = threadIdx.x & (D - 1);
    const int rib = threadIdx.x >> 6;
    const int stride = (blockDim.x / D) * gridDim.x;
    float s = 0.f, sq = 0.f;
    for (int r = blockIdx.x * (blockDim.x / D) + rib; r < NN; r += stride) {
        float v = g_h1[(size_t)r * D + col];
        s += v; sq += v * v;
    }
    __shared__ __align__(16) float sh[256];
    __shared__ __align__(16) float shq[256];
    sh[threadIdx.x] = s; shq[threadIdx.x] = sq;
    __syncthreads();
    if (threadIdx.x < D) {
        float ts = sh[threadIdx.x] + sh[threadIdx.x + 64] +
                   sh[threadIdx.x + 128] + sh[threadIdx.x + 192];
        float tq = shq[threadIdx.x] + shq[threadIdx.x + 64] +
                   shq[threadIdx.x + 128] + shq[threadIdx.x + 192];
        atomicAdd(&g_sum[threadIdx.x], ts);
        atomicAdd(&g_sumsq[threadIdx.x], tq);
    }
}

// ---------------------------------------------------------------------------
// 8: out = relu(BN(h1)) @ W2 + b2, BN folded into per-column scale/shift
// ---------------------------------------------------------------------------
__global__ void __launch_bounds__(128) k_gemm2(const float* __restrict__ W2,
                                               const float* __restrict__ b2,
                                               const float* __restrict__ gamma,
                                               const float* __restrict__ beta,
                                               float* __restrict__ out) {
    __shared__ __align__(16) float Ws[D * D];
    __shared__ __align__(16) float scl[D];
    __shared__ __align__(16) float sft[D];
    __shared__ __align__(16) float bs[D];
    const int tid = threadIdx.x;
    for (int i = tid; i < D * D; i += blockDim.x) Ws[i] = W2[i];
    if (tid < D) {
        const float inv_n = 1.f / (float)NN;
        float mean = g_sum[tid] * inv_n;
        float var  = g_sumsq[tid] * inv_n - mean * mean;
        float rstd = rsqrtf(var + BN_EPS);
        float s = rstd * gamma[tid];
        scl[tid] = s;
        sft[tid] = beta[tid] - mean * s;
        bs[tid]  = b2[tid];
    }
    __syncthreads();

    const int row = blockIdx.x * blockDim.x + tid;
    if (row >= NN) return;

    float acc[D];
#pragma unroll
    for (int j = 0; j < D; j++) acc[j] = 0.f;

    const float4* __restrict__ hr = (const float4*)(g_h1 + (size_t)row * D);
    for (int k4 = 0; k4 < D / 4; k4++) {
        float4 hv = hr[k4];
#pragma unroll
        for (int kk = 0; kk < 4; kk++) {
            const int k = k4 * 4 + kk;
            float hk = ((const float*)&hv)[kk];
            hk = fmaxf(hk * scl[k] + sft[k], 0.f);        // BN + ReLU
            const float4* wrow = (const float4*)&Ws[k * D];
#pragma unroll
            for (int j4 = 0; j4 < D / 4; j4++) {
                float4 w = wrow[j4];
                acc[j4 * 4 + 0] += hk * w.x;
                acc[j4 * 4 + 1] += hk * w.y;
                acc[j4 * 4 + 2] += hk * w.z;
                acc[j4 * 4 + 3] += hk * w.w;
            }
        }
    }
    float4* o4 = (float4*)(out + (size_t)row * D);
#pragma unroll
    for (int j4 = 0; j4 < D / 4; j4++) {
        float4 o;
        o.x = acc[j4 * 4 + 0] + bs[j4 * 4 + 0];
        o.y = acc[j4 * 4 + 1] + bs[j4 * 4 + 1];
        o.z = acc[j4 * 4 + 2] + bs[j4 * 4 + 2];
        o.w = acc[j4 * 4 + 3] + bs[j4 * 4 + 3];
        o4[j4] = o;
    }
}

// ---------------------------------------------------------------------------
extern "C" void kernel_launch(void* const* d_in, const int* in_sizes, int n_in,
                              void* d_out, int out_size) {
    const float* x     = (const float*)d_in[0];
    const int*   ei    = (const int*)  d_in[1];   // int32 (JAX demotes int64)
    const float* eps   = (const float*)d_in[2];
    const float* W1    = (const float*)d_in[3];
    const float* b1    = (const float*)d_in[4];
    const float* gamma = (const float*)d_in[5];
    const float* beta  = (const float*)d_in[6];
    const float* W2    = (const float*)d_in[7];
    const float* b2    = (const float*)d_in[8];
    float* out = (float*)d_out;

    k_zero  <<<(NN + 255) / 256, 256>>>();
    k_deg   <<<(EE + 255) / 256, 256>>>(ei);
    k_scan_a<<<NBLK, SB>>>();
    k_scan_b<<<1, 128>>>();
    k_scan_c<<<NBLK, SB>>>();
    k_fill  <<<(EE + 255) / 256, 256>>>(ei);
    k_gather<<<(NN * 32 + 255) / 256, 256>>>(x, eps);
    k_gemm1 <<<(NN + 127) / 128, 128>>>(W1, b1);
    k_stats <<<256, 256>>>();
    k_gemm2 <<<(NN + 127) / 128, 128>>>(W2, b2, gamma, beta, out);
}